// round 6
// baseline (speedup 1.0000x reference)
#include <cuda_runtime.h>

// Kalman filter: B=4096 batches, T=200 steps, S=8 state, M=2 obs.
// 8 threads per batch (one per state row), 32 batches per 256-thread block,
// 128 blocks. All cross-row communication through a per-batch SMEM workspace
// (stride 328 floats => the 4 batch-groups of a warp land on disjoint banks).
// Only warp-level sync is needed (4 __syncwarp per step).

namespace {
constexpr int Bb  = 4096;
constexpr int Tt  = 200;
constexpr int Ssz = 8;
constexpr int BPB = 32;   // batches per block
constexpr int WSF = 328;  // workspace floats per batch (mod 32 == 8, 16B-aligned)
}

__global__ __launch_bounds__(256, 1)
void kalman_kernel(const float* __restrict__ gy,      // [B,T,2]
                   const float* __restrict__ gF,      // [B,T,8,8]
                   const float* __restrict__ gH,      // [B,T,2,8]
                   const float* __restrict__ gQ,      // [8,8]
                   const float* __restrict__ gR,      // [2,2]
                   const float* __restrict__ gMean0,  // [B,8]
                   const float* __restrict__ gCov0,   // [8,8]
                   float* __restrict__ oMean,         // [B,T,8]
                   float* __restrict__ oCov)          // [B,T,8,8]
{
    __shared__ __align__(16) float sw[BPB * WSF];
    const int tid = threadIdx.x;
    const int lb  = tid >> 3;   // local batch within block
    const int i   = tid & 7;    // state row owned by this thread
    const int b   = blockIdx.x * BPB + lb;

    float* wsp   = sw + lb * WSF;
    float* sP    = wsp;         // 64: state covariance
    float* sCU   = wsp + 64;    // 64: updated covariance
    float* sF    = wsp + 128;   // 64: F_t
    float* sIK   = wsp + 192;   // 64: I - K H
    float* sHP   = wsp + 256;   // 16: H P
    float* sW    = wsp + 272;   // 16: W = S^{-1} (H P)  (K = W^T)
    float* sMU   = wsp + 288;   //  8: updated mean
    float* sMean = wsp + 296;   //  8: state mean

    // Constants (loop-invariant)
    const float R00 = gR[0], R01 = gR[1], R10 = gR[2], R11 = gR[3];
    float Qr[8];
#pragma unroll
    for (int k = 0; k < 8; ++k) Qr[k] = gQ[i * 8 + k];

    // ---- init state + t=0 outputs ----
    const float4 ic0 = *(const float4*)(gCov0 + i * 8);
    const float4 ic1 = *(const float4*)(gCov0 + i * 8 + 4);
    *(float4*)(sP + i * 8)     = ic0;
    *(float4*)(sP + i * 8 + 4) = ic1;
    const float m0i = gMean0[b * 8 + i];
    sMean[i] = m0i;

    float* omb = oMean + (size_t)b * Tt * 8;
    float* ocb = oCov  + (size_t)b * Tt * 64;
    omb[i] = m0i;
    *(float4*)(ocb + i * 8)     = ic0;
    *(float4*)(ocb + i * 8 + 4) = ic1;

    const float* Fb = gF + (size_t)b * Tt * 64;
    const float* Hb = gH + (size_t)b * Tt * 16;
    const float* yb = gy + (size_t)b * Tt * 2;

    // ---- prefetch step 0 inputs ----
    float4 f0 = *(const float4*)(Fb + i * 8);
    float4 f1 = *(const float4*)(Fb + i * 8 + 4);
    float4 h0 = *(const float4*)(Hb);
    float4 h1 = *(const float4*)(Hb + 4);
    float4 h2 = *(const float4*)(Hb + 8);
    float4 h3 = *(const float4*)(Hb + 12);
    float2 yv = *(const float2*)(yb);

    __syncwarp();

    for (int t = 0; t < Tt - 1; ++t) {
        // Current-step operands (copied so the prefetch below can reuse regs)
        const float fr[8]  = {f0.x, f0.y, f0.z, f0.w, f1.x, f1.y, f1.z, f1.w};
        const float ha[8]  = {h0.x, h0.y, h0.z, h0.w, h1.x, h1.y, h1.z, h1.w};
        const float hc[8]  = {h2.x, h2.y, h2.z, h2.w, h3.x, h3.y, h3.z, h3.w};
        const float y0 = yv.x, y1 = yv.y;

        // Prefetch next step (t+1 <= T-1, always in bounds)
        {
            const float* Fn = Fb + (size_t)(t + 1) * 64;
            f0 = *(const float4*)(Fn + i * 8);
            f1 = *(const float4*)(Fn + i * 8 + 4);
            const float* Hn = Hb + (size_t)(t + 1) * 16;
            h0 = *(const float4*)(Hn);
            h1 = *(const float4*)(Hn + 4);
            h2 = *(const float4*)(Hn + 8);
            h3 = *(const float4*)(Hn + 12);
            yv = *(const float2*)(yb + (size_t)(t + 1) * 2);
        }

        // F row into SMEM (needed by all rows in the predict stage)
        *(float4*)(sF + i * 8)     = make_float4(fr[0], fr[1], fr[2], fr[3]);
        *(float4*)(sF + i * 8 + 4) = make_float4(fr[4], fr[5], fr[6], fr[7]);

        // ---- HP = H P : thread i computes column i (conflict-free column read) ----
        float hp0 = 0.f, hp1 = 0.f;
#pragma unroll
        for (int s = 0; s < 8; ++s) {
            const float p = sP[s * 8 + i];
            hp0 += ha[s] * p;
            hp1 += hc[s] * p;
        }
        sHP[i]     = hp0;
        sHP[8 + i] = hp1;
        __syncwarp();  // sync A: sHP, sF visible

        // ---- full HP rows (broadcast) ----
        float HP0[8], HP1[8];
        {
            float4 a = *(const float4*)(sHP);
            float4 c = *(const float4*)(sHP + 4);
            HP0[0]=a.x; HP0[1]=a.y; HP0[2]=a.z; HP0[3]=a.w;
            HP0[4]=c.x; HP0[5]=c.y; HP0[6]=c.z; HP0[7]=c.w;
            a = *(const float4*)(sHP + 8);
            c = *(const float4*)(sHP + 12);
            HP1[0]=a.x; HP1[1]=a.y; HP1[2]=a.z; HP1[3]=a.w;
            HP1[4]=c.x; HP1[5]=c.y; HP1[6]=c.z; HP1[7]=c.w;
        }

        // ---- Smat = HP H^T + R (keep both off-diagonals like the reference) ----
        float s00 = R00, s01 = R01, s10 = R10, s11 = R11;
#pragma unroll
        for (int k = 0; k < 8; ++k) {
            s00 += HP0[k] * ha[k];
            s01 += HP0[k] * hc[k];
            s10 += HP1[k] * ha[k];
            s11 += HP1[k] * hc[k];
        }
        const float inv = 1.0f / (s00 * s11 - s01 * s10);

        // W = S^{-1} HP; this thread only needs column i (K[i][m] = W[m][i])
        const float w0i = inv * ( s11 * hp0 - s01 * hp1);
        const float w1i = inv * (-s10 * hp0 + s00 * hp1);
        sW[i]     = w0i;
        sW[8 + i] = w1i;

        // ---- residual (redundant per thread) ----
        float mn[8];
        {
            const float4 a = *(const float4*)(sMean);
            const float4 c = *(const float4*)(sMean + 4);
            mn[0]=a.x; mn[1]=a.y; mn[2]=a.z; mn[3]=a.w;
            mn[4]=c.x; mn[5]=c.y; mn[6]=c.z; mn[7]=c.w;
        }
        float r0 = y0, r1 = y1;
#pragma unroll
        for (int s = 0; s < 8; ++s) {
            r0 -= ha[s] * mn[s];
            r1 -= hc[s] * mn[s];
        }

        // mean_u element i
        sMU[i] = mn[i] + w0i * r0 + w1i * r1;

        // ---- ImKH row i ----
        float ik[8];
#pragma unroll
        for (int k = 0; k < 8; ++k)
            ik[k] = (i == k ? 1.0f : 0.0f) - w0i * ha[k] - w1i * hc[k];
        *(float4*)(sIK + i * 8)     = make_float4(ik[0], ik[1], ik[2], ik[3]);
        *(float4*)(sIK + i * 8 + 4) = make_float4(ik[4], ik[5], ik[6], ik[7]);
        __syncwarp();  // sync B: sW, sMU, sIK visible

        // ---- A = ImKH_row_i @ P ----
        float acc[8] = {0, 0, 0, 0, 0, 0, 0, 0};
#pragma unroll
        for (int j = 0; j < 8; ++j) {
            const float4 p0 = *(const float4*)(sP + j * 8);
            const float4 p1 = *(const float4*)(sP + j * 8 + 4);
            const float c = ik[j];
            acc[0] += c * p0.x; acc[1] += c * p0.y;
            acc[2] += c * p0.z; acc[3] += c * p0.w;
            acc[4] += c * p1.x; acc[5] += c * p1.y;
            acc[6] += c * p1.z; acc[7] += c * p1.w;
        }

        // KRK^T row-i coefficients: V[n][i] = sum_m R[m][n] W[m][i]
        const float v0 = R00 * w0i + R10 * w1i;
        const float v1 = R01 * w0i + R11 * w1i;
        float w0[8], w1[8];
        {
            float4 a = *(const float4*)(sW);
            float4 c = *(const float4*)(sW + 4);
            w0[0]=a.x; w0[1]=a.y; w0[2]=a.z; w0[3]=a.w;
            w0[4]=c.x; w0[5]=c.y; w0[6]=c.z; w0[7]=c.w;
            a = *(const float4*)(sW + 8);
            c = *(const float4*)(sW + 12);
            w1[0]=a.x; w1[1]=a.y; w1[2]=a.z; w1[3]=a.w;
            w1[4]=c.x; w1[5]=c.y; w1[6]=c.z; w1[7]=c.w;
        }

        // ---- cov_u row i = A @ ImKH^T + K R K^T ----
        float cu[8];
#pragma unroll
        for (int k = 0; k < 8; ++k) {
            const float4 q0 = *(const float4*)(sIK + k * 8);
            const float4 q1 = *(const float4*)(sIK + k * 8 + 4);
            float ta = v0 * w0[k] + v1 * w1[k];
            ta += acc[0] * q0.x + acc[1] * q0.y + acc[2] * q0.z + acc[3] * q0.w
                + acc[4] * q1.x + acc[5] * q1.y + acc[6] * q1.z + acc[7] * q1.w;
            cu[k] = ta;
        }

        // ---- mean_p row i = F_row_i @ mean_u ----
        float mu[8];
        {
            const float4 a = *(const float4*)(sMU);
            const float4 c = *(const float4*)(sMU + 4);
            mu[0]=a.x; mu[1]=a.y; mu[2]=a.z; mu[3]=a.w;
            mu[4]=c.x; mu[5]=c.y; mu[6]=c.z; mu[7]=c.w;
        }
        float mp = 0.f;
#pragma unroll
        for (int j = 0; j < 8; ++j) mp += fr[j] * mu[j];
        omb[(size_t)(t + 1) * 8 + i] = mp;
        sMean[i] = mp;  // safe: all sMean reads happened before sync B

        *(float4*)(sCU + i * 8)     = make_float4(cu[0], cu[1], cu[2], cu[3]);
        *(float4*)(sCU + i * 8 + 4) = make_float4(cu[4], cu[5], cu[6], cu[7]);
        __syncwarp();  // sync C: sCU visible; sP reads complete

        // ---- G = F_row_i @ cov_u ----
        float g[8] = {0, 0, 0, 0, 0, 0, 0, 0};
#pragma unroll
        for (int j = 0; j < 8; ++j) {
            const float4 c0 = *(const float4*)(sCU + j * 8);
            const float4 c1 = *(const float4*)(sCU + j * 8 + 4);
            const float c = fr[j];
            g[0] += c * c0.x; g[1] += c * c0.y;
            g[2] += c * c0.z; g[3] += c * c0.w;
            g[4] += c * c1.x; g[5] += c * c1.y;
            g[6] += c * c1.z; g[7] += c * c1.w;
        }

        // ---- P' row i = G @ F^T + Q ----
        float pn[8];
#pragma unroll
        for (int k = 0; k < 8; ++k) {
            const float4 q0 = *(const float4*)(sF + k * 8);
            const float4 q1 = *(const float4*)(sF + k * 8 + 4);
            pn[k] = Qr[k]
                  + g[0] * q0.x + g[1] * q0.y + g[2] * q0.z + g[3] * q0.w
                  + g[4] * q1.x + g[5] * q1.y + g[6] * q1.z + g[7] * q1.w;
        }
        *(float4*)(sP + i * 8)     = make_float4(pn[0], pn[1], pn[2], pn[3]);
        *(float4*)(sP + i * 8 + 4) = make_float4(pn[4], pn[5], pn[6], pn[7]);

        float* oc = ocb + (size_t)(t + 1) * 64 + i * 8;
        *(float4*)(oc)     = make_float4(pn[0], pn[1], pn[2], pn[3]);
        *(float4*)(oc + 4) = make_float4(pn[4], pn[5], pn[6], pn[7]);
        __syncwarp();  // sync D: sP, sMean visible for next iteration
    }
}

extern "C" void kernel_launch(void* const* d_in, const int* in_sizes, int n_in,
                              void* d_out, int out_size)
{
    // metadata order: y, F, H, Q, R, init_mean, init_cov, n_step
    const float* gy     = (const float*)d_in[0];
    const float* gF     = (const float*)d_in[1];
    const float* gH     = (const float*)d_in[2];
    const float* gQ     = (const float*)d_in[3];
    const float* gR     = (const float*)d_in[4];
    const float* gMean0 = (const float*)d_in[5];
    const float* gCov0  = (const float*)d_in[6];
    (void)in_sizes; (void)n_in;

    float* oMean = (float*)d_out;                               // [B,T,8]
    float* oCov  = (float*)d_out + (size_t)Bb * Tt * Ssz;       // [B,T,8,8]
    (void)out_size;

    kalman_kernel<<<Bb / BPB, BPB * Ssz>>>(gy, gF, gH, gQ, gR, gMean0, gCov0,
                                           oMean, oCov);
}

// round 7
// speedup vs baseline: 1.4380x; 1.4380x over previous
#include <cuda_runtime.h>

// Kalman filter, fused-congruence formulation.
// B=4096, T=200, S=8, M=2. 8 threads per batch (thread = state row),
// 4 batches per 32-thread block, 1024 blocks (6-7 warps/SM everywhere).
//
// Per step (cov_u never materialized):
//   HP  = H P            (P row from own registers; P symmetric)
//   S   = HP H^T + R ; W = S^{-1} HP ; K = W^T
//   C   = F K  (8x2, via sW broadcast) ; Z = F - C H  (registers only)
//   mean' = fr.mn + C.r
//   P'  = Z P Z^T + C R C^T + Q   (two broadcast matmuls: sP rows, sZ rows)
// SMEM crossbar cost/warp/step ~206 cycles vs ~350 in the 4-matmul version.

namespace {
constexpr int Bb  = 4096;
constexpr int Tt  = 200;
constexpr int BPB = 4;     // batches per block
constexpr int WSF = 200;   // workspace stride (mod 32 == 8, 16B-aligned)
}

__global__ __launch_bounds__(32)
void kalman_kernel(const float* __restrict__ gy,      // [B,T,2]
                   const float* __restrict__ gF,      // [B,T,8,8]
                   const float* __restrict__ gH,      // [B,T,2,8]
                   const float* __restrict__ gQ,      // [8,8]
                   const float* __restrict__ gR,      // [2,2]
                   const float* __restrict__ gMean0,  // [B,8]
                   const float* __restrict__ gCov0,   // [8,8]
                   float* __restrict__ oMean,         // [B,T,8]
                   float* __restrict__ oCov)          // [B,T,8,8]
{
    __shared__ __align__(16) float sw[BPB * WSF];
    const int tid = threadIdx.x;
    const int lb  = tid >> 3;   // local batch
    const int i   = tid & 7;    // state row owned by this thread
    const int b   = blockIdx.x * BPB + lb;

    float* wsp   = sw + lb * WSF;
    float* sP    = wsp;          // 64: state covariance (predicted)
    float* sZ    = wsp + 64;     // 64: Z = F(I-KH)
    float* sHP   = wsp + 128;    // 16: H P
    float* sWm   = wsp + 144;    // 16: W = S^{-1} HP  (K = W^T)
    float* sC    = wsp + 160;    // 16: C rows, (c0,c1) interleaved per row
    float* sMean = wsp + 176;    //  8: predicted mean

    // Loop-invariant constants
    const float R00 = gR[0], R01 = gR[1], R10 = gR[2], R11 = gR[3];
    float Qr[8];
#pragma unroll
    for (int k = 0; k < 8; ++k) Qr[k] = gQ[i * 8 + k];

    // ---- init state + t=0 outputs ----
    float pr[8];  // own row of P, kept in registers
    {
        const float4 ic0 = *(const float4*)(gCov0 + i * 8);
        const float4 ic1 = *(const float4*)(gCov0 + i * 8 + 4);
        pr[0]=ic0.x; pr[1]=ic0.y; pr[2]=ic0.z; pr[3]=ic0.w;
        pr[4]=ic1.x; pr[5]=ic1.y; pr[6]=ic1.z; pr[7]=ic1.w;
        *(float4*)(sP + i * 8)     = ic0;
        *(float4*)(sP + i * 8 + 4) = ic1;
        float* ocb0 = oCov + (size_t)b * Tt * 64 + i * 8;
        *(float4*)(ocb0)     = ic0;
        *(float4*)(ocb0 + 4) = ic1;
    }
    const float m0i = gMean0[b * 8 + i];
    sMean[i] = m0i;
    oMean[(size_t)b * Tt * 8 + i] = m0i;

    const float* Fb = gF + (size_t)b * Tt * 64;
    const float* Hb = gH + (size_t)b * Tt * 16;
    const float* yb = gy + (size_t)b * Tt * 2;
    float* omb = oMean + (size_t)b * Tt * 8;
    float* ocb = oCov  + (size_t)b * Tt * 64;

    // ---- prefetch step 0 inputs ----
    float4 f0 = *(const float4*)(Fb + i * 8);
    float4 f1 = *(const float4*)(Fb + i * 8 + 4);
    float4 h0 = *(const float4*)(Hb);
    float4 h1 = *(const float4*)(Hb + 4);
    float4 h2 = *(const float4*)(Hb + 8);
    float4 h3 = *(const float4*)(Hb + 12);
    float2 yv = *(const float2*)(yb);

    __syncwarp();

    for (int t = 0; t < Tt - 1; ++t) {
        // current-step operands (copies free the prefetch registers)
        const float fr[8] = {f0.x, f0.y, f0.z, f0.w, f1.x, f1.y, f1.z, f1.w};
        const float ha[8] = {h0.x, h0.y, h0.z, h0.w, h1.x, h1.y, h1.z, h1.w};
        const float hc[8] = {h2.x, h2.y, h2.z, h2.w, h3.x, h3.y, h3.z, h3.w};
        const float y0 = yv.x, y1 = yv.y;

        // prefetch next step (t+1 <= T-1 always valid)
        {
            const float* Fn = Fb + (size_t)(t + 1) * 64;
            f0 = *(const float4*)(Fn + i * 8);
            f1 = *(const float4*)(Fn + i * 8 + 4);
            const float* Hn = Hb + (size_t)(t + 1) * 16;
            h0 = *(const float4*)(Hn);
            h1 = *(const float4*)(Hn + 4);
            h2 = *(const float4*)(Hn + 8);
            h3 = *(const float4*)(Hn + 12);
            yv = *(const float2*)(yb + (size_t)(t + 1) * 2);
        }

        // ---- HP column i, using own register row (P symmetric) ----
        float hp0 = 0.f, hp1 = 0.f;
#pragma unroll
        for (int s = 0; s < 8; ++s) {
            hp0 += ha[s] * pr[s];
            hp1 += hc[s] * pr[s];
        }
        sHP[i]     = hp0;
        sHP[8 + i] = hp1;
        __syncwarp();  // sync A: sHP visible

        // ---- full HP rows + mean (broadcast reads) ----
        float HP0[8], HP1[8], mn[8];
        {
            float4 a = *(const float4*)(sHP);
            float4 c = *(const float4*)(sHP + 4);
            HP0[0]=a.x; HP0[1]=a.y; HP0[2]=a.z; HP0[3]=a.w;
            HP0[4]=c.x; HP0[5]=c.y; HP0[6]=c.z; HP0[7]=c.w;
            a = *(const float4*)(sHP + 8);
            c = *(const float4*)(sHP + 12);
            HP1[0]=a.x; HP1[1]=a.y; HP1[2]=a.z; HP1[3]=a.w;
            HP1[4]=c.x; HP1[5]=c.y; HP1[6]=c.z; HP1[7]=c.w;
            a = *(const float4*)(sMean);
            c = *(const float4*)(sMean + 4);
            mn[0]=a.x; mn[1]=a.y; mn[2]=a.z; mn[3]=a.w;
            mn[4]=c.x; mn[5]=c.y; mn[6]=c.z; mn[7]=c.w;
        }

        // ---- Smat = HP H^T + R (both off-diagonals, like the reference) ----
        float s00 = R00, s01 = R01, s10 = R10, s11 = R11;
        float r0 = y0, r1 = y1;
#pragma unroll
        for (int k = 0; k < 8; ++k) {
            s00 += HP0[k] * ha[k];
            s01 += HP0[k] * hc[k];
            s10 += HP1[k] * ha[k];
            s11 += HP1[k] * hc[k];
            r0  -= ha[k] * mn[k];
            r1  -= hc[k] * mn[k];
        }
        const float inv = 1.0f / (s00 * s11 - s01 * s10);

        // W = S^{-1} HP, own column i
        const float w0i = inv * ( s11 * hp0 - s01 * hp1);
        const float w1i = inv * (-s10 * hp0 + s00 * hp1);
        sWm[i]     = w0i;
        sWm[8 + i] = w1i;
        __syncwarp();  // sync B: sW visible

        // ---- C row i = F_row_i @ K  (K[j][m] = W[m][j]) ----
        float c0 = 0.f, c1 = 0.f;
        {
            float4 a = *(const float4*)(sWm);
            float4 c = *(const float4*)(sWm + 4);
            c0 += fr[0]*a.x + fr[1]*a.y + fr[2]*a.z + fr[3]*a.w;
            c0 += fr[4]*c.x + fr[5]*c.y + fr[6]*c.z + fr[7]*c.w;
            a = *(const float4*)(sWm + 8);
            c = *(const float4*)(sWm + 12);
            c1 += fr[0]*a.x + fr[1]*a.y + fr[2]*a.z + fr[3]*a.w;
            c1 += fr[4]*c.x + fr[5]*c.y + fr[6]*c.z + fr[7]*c.w;
        }

        // ---- Z row i = fr - c0*ha - c1*hc  (registers only) ----
        float z[8];
#pragma unroll
        for (int k = 0; k < 8; ++k)
            z[k] = fr[k] - c0 * ha[k] - c1 * hc[k];
        *(float4*)(sZ + i * 8)     = make_float4(z[0], z[1], z[2], z[3]);
        *(float4*)(sZ + i * 8 + 4) = make_float4(z[4], z[5], z[6], z[7]);
        *(float2*)(sC + 2 * i)     = make_float2(c0, c1);

        // ---- mean_p = fr.mn + C_row_i . resid ----
        float mp = c0 * r0 + c1 * r1;
#pragma unroll
        for (int j = 0; j < 8; ++j) mp += fr[j] * mn[j];

        // ---- A = Z_row_i @ P (broadcast rows of old P) ----
        float acc[8] = {0, 0, 0, 0, 0, 0, 0, 0};
#pragma unroll
        for (int j = 0; j < 8; ++j) {
            const float4 p0 = *(const float4*)(sP + j * 8);
            const float4 p1 = *(const float4*)(sP + j * 8 + 4);
            const float c = z[j];
            acc[0] += c * p0.x; acc[1] += c * p0.y;
            acc[2] += c * p0.z; acc[3] += c * p0.w;
            acc[4] += c * p1.x; acc[5] += c * p1.y;
            acc[6] += c * p1.z; acc[7] += c * p1.w;
        }
        __syncwarp();  // sync C: sZ, sC visible; all reads of old sP complete

        // ---- C R C^T coefficients + C rows ----
        const float v0 = R00 * c0 + R10 * c1;
        const float v1 = R01 * c0 + R11 * c1;
        float cp0[8], cp1[8];
        {
            float4 a = *(const float4*)(sC);        // c0[0],c1[0],c0[1],c1[1]
            float4 c = *(const float4*)(sC + 4);
            cp0[0]=a.x; cp1[0]=a.y; cp0[1]=a.z; cp1[1]=a.w;
            cp0[2]=c.x; cp1[2]=c.y; cp0[3]=c.z; cp1[3]=c.w;
            a = *(const float4*)(sC + 8);
            c = *(const float4*)(sC + 12);
            cp0[4]=a.x; cp1[4]=a.y; cp0[5]=a.z; cp1[5]=a.w;
            cp0[6]=c.x; cp1[6]=c.y; cp0[7]=c.z; cp1[7]=c.w;
        }

        // ---- P' row i = A @ Z^T + v.C^T + Q ----
        float pn[8];
#pragma unroll
        for (int k = 0; k < 8; ++k) {
            const float4 q0 = *(const float4*)(sZ + k * 8);
            const float4 q1 = *(const float4*)(sZ + k * 8 + 4);
            float ta = Qr[k] + v0 * cp0[k] + v1 * cp1[k];
            ta += acc[0] * q0.x + acc[1] * q0.y + acc[2] * q0.z + acc[3] * q0.w
                + acc[4] * q1.x + acc[5] * q1.y + acc[6] * q1.z + acc[7] * q1.w;
            pn[k] = ta;
        }
#pragma unroll
        for (int k = 0; k < 8; ++k) pr[k] = pn[k];

        // commit state + outputs
        sMean[i] = mp;  // all sMean reads happened before sync B
        const float4 pnl = make_float4(pn[0], pn[1], pn[2], pn[3]);
        const float4 pnh = make_float4(pn[4], pn[5], pn[6], pn[7]);
        *(float4*)(sP + i * 8)     = pnl;
        *(float4*)(sP + i * 8 + 4) = pnh;

        omb[(size_t)(t + 1) * 8 + i] = mp;
        float* oc = ocb + (size_t)(t + 1) * 64 + i * 8;
        *(float4*)(oc)     = pnl;
        *(float4*)(oc + 4) = pnh;
        __syncwarp();  // sync D: sP, sMean visible for next iteration
    }
}

extern "C" void kernel_launch(void* const* d_in, const int* in_sizes, int n_in,
                              void* d_out, int out_size)
{
    // metadata order: y, F, H, Q, R, init_mean, init_cov, n_step
    const float* gy     = (const float*)d_in[0];
    const float* gF     = (const float*)d_in[1];
    const float* gH     = (const float*)d_in[2];
    const float* gQ     = (const float*)d_in[3];
    const float* gR     = (const float*)d_in[4];
    const float* gMean0 = (const float*)d_in[5];
    const float* gCov0  = (const float*)d_in[6];
    (void)in_sizes; (void)n_in;

    float* oMean = (float*)d_out;                          // [B,T,8]
    float* oCov  = (float*)d_out + (size_t)Bb * Tt * 8;    // [B,T,8,8]
    (void)out_size;

    kalman_kernel<<<Bb / BPB, BPB * 8>>>(gy, gF, gH, gQ, gR, gMean0, gCov0,
                                         oMean, oCov);
}